// round 3
// baseline (speedup 1.0000x reference)
#include <cuda_runtime.h>
#include <cuda_bf16.h>
#include <cstdint>
#include <math_constants.h>

#define BB 2
#define SS 2048
#define DD 1024
#define HH 16
#define DKK 64
#define MTOT (BB * SS)   // 4096

// ---------------------------------------------------------------------------
// Scratch (device globals; no allocation allowed)
// ---------------------------------------------------------------------------
__device__ float g_Q[MTOT * DD];
__device__ float g_K[MTOT * DD];
__device__ float g_V[MTOT * DD];
__device__ float g_A[MTOT * DD];
__device__ __nv_bfloat16 g_Xhi[MTOT * DD];
__device__ __nv_bfloat16 g_Xlo[MTOT * DD];
__device__ __nv_bfloat16 g_Whi[DD * DD];
__device__ __nv_bfloat16 g_Wlo[DD * DD];

// ---------------------------------------------------------------------------
// Helpers (sm_80-level PTX only: mma.sync / ldmatrix / cp.async)
// ---------------------------------------------------------------------------
__device__ __forceinline__ uint32_t smem_u32(const void* p) {
    uint32_t a;
    asm("{ .reg .u64 t; cvta.to.shared.u64 t, %1; cvt.u32.u64 %0, t; }" : "=r"(a) : "l"(p));
    return a;
}
__device__ __forceinline__ void cp16(uint32_t dst, const void* src) {
    asm volatile("cp.async.cg.shared.global [%0], [%1], 16;" :: "r"(dst), "l"(src));
}
#define CP_COMMIT() asm volatile("cp.async.commit_group;" ::: "memory")
#define CP_WAIT1()  asm volatile("cp.async.wait_group 1;" ::: "memory")
#define CP_WAIT0()  asm volatile("cp.async.wait_group 0;" ::: "memory")

__device__ __forceinline__ void ldmx4(uint32_t* r, uint32_t addr) {
    asm volatile("ldmatrix.sync.aligned.m8n8.x4.shared.b16 {%0,%1,%2,%3}, [%4];"
                 : "=r"(r[0]), "=r"(r[1]), "=r"(r[2]), "=r"(r[3]) : "r"(addr));
}
__device__ __forceinline__ void mma16816(float* c, const uint32_t* a, const uint32_t* b) {
    asm volatile(
        "mma.sync.aligned.m16n8k16.row.col.f32.bf16.bf16.f32 "
        "{%0,%1,%2,%3}, {%4,%5,%6,%7}, {%8,%9}, {%0,%1,%2,%3};"
        : "+f"(c[0]), "+f"(c[1]), "+f"(c[2]), "+f"(c[3])
        : "r"(a[0]), "r"(a[1]), "r"(a[2]), "r"(a[3]), "r"(b[0]), "r"(b[1]));
}

// ---------------------------------------------------------------------------
// Split fp32 -> bf16 hi/lo  (x = hi + lo + O(2^-18 x))
// ---------------------------------------------------------------------------
__global__ void split_bf16(const float* __restrict__ x, __nv_bfloat16* __restrict__ hi,
                           __nv_bfloat16* __restrict__ lo, int n4)
{
    int i = blockIdx.x * blockDim.x + threadIdx.x;
    if (i >= n4) return;
    float4 v = ((const float4*)x)[i];
    float vv[4] = {v.x, v.y, v.z, v.w};
    union { __nv_bfloat16 b[4]; uint2 u; } H, L;
#pragma unroll
    for (int j = 0; j < 4; j++) {
        __nv_bfloat16 h = __float2bfloat16(vv[j]);
        H.b[j] = h;
        L.b[j] = __float2bfloat16(vv[j] - __bfloat162float(h));
    }
    ((uint2*)hi)[i] = H.u;
    ((uint2*)lo)[i] = L.u;
}

// ---------------------------------------------------------------------------
// HMMA bf16x3 GEMM: C[4096,1024] = A @ W^T + bias
// CTA 128x128, BK=32, 8 warps in 2(M)x4(N), warp tile 64x32.
// smem tile layout: 128 rows x 32 bf16 (64B) padded to 80B stride
// (conflict-free for ldmatrix: banks(20r+c) distinct over r=0..7).
// Double-buffered with cp.async. Tiles per stage: Ahi, Alo, Whi, Wlo.
// ---------------------------------------------------------------------------
#define TILE_B 10240               // 128 * 80
#define STAGE_B (4 * TILE_B)       // 40960
#define GEMM_SMEM (2 * STAGE_B)    // 81920

__global__ __launch_bounds__(256)
void gemm_mma(const __nv_bfloat16* __restrict__ Ahi, const __nv_bfloat16* __restrict__ Alo,
              const __nv_bfloat16* __restrict__ Whi, const __nv_bfloat16* __restrict__ Wlo,
              const float* __restrict__ bias, float* __restrict__ C)
{
    extern __shared__ __align__(128) char smem[];
    const uint32_t sb = smem_u32(smem);
    const int tid = threadIdx.x;
    const int wid = tid >> 5;
    const int lane = tid & 31;
    const int bm = blockIdx.y * 128;
    const int bn = blockIdx.x * 128;
    const int warpM = wid >> 2;    // 0..1
    const int warpN = wid & 3;     // 0..3

    const char* srcs[4] = {
        (const char*)(Ahi + (size_t)bm * DD),
        (const char*)(Alo + (size_t)bm * DD),
        (const char*)(Whi + (size_t)bn * DD),
        (const char*)(Wlo + (size_t)bn * DD)
    };

    float acc[4][4][4];
#pragma unroll
    for (int i = 0; i < 4; i++)
#pragma unroll
        for (int j = 0; j < 4; j++)
#pragma unroll
            for (int q = 0; q < 4; q++) acc[i][j][q] = 0.f;

    // ldmatrix lane addressing
    const int lr = lane & 7;
    const int lb8 = (lane >> 3) & 1;
    const int lb16 = (lane >> 4) & 1;
    // A-type (rows = output rows, 4 tiles of 16): row = lr + lb8*8, khalf = lb16
    const uint32_t a_off = (uint32_t)((lr + lb8 * 8) * 80 + lb16 * 16) + (uint32_t)(warpM * 64 * 80);
    // B-type (rows = n, pair of ntiles): n = lr + lb16*8, khalf = lb8
    const uint32_t b_off = (uint32_t)((lr + lb16 * 8) * 80 + lb8 * 16) + (uint32_t)(warpN * 32 * 80);

    // --- stage loader ---
    auto load_stage = [&](int stage, int c) {
#pragma unroll
        for (int t = 0; t < 4; t++) {
            uint32_t base = sb + stage * STAGE_B + t * TILE_B;
            const char* g = srcs[t] + c * 64;       // c*32 bf16 = 64 bytes
#pragma unroll
            for (int j = 0; j < 2; j++) {
                int chunk = tid + j * 256;          // 0..511
                int row = chunk >> 2;
                int cw = chunk & 3;
                cp16(base + (uint32_t)(row * 80 + cw * 16), g + (size_t)row * 2048 + cw * 16);
            }
        }
        CP_COMMIT();
    };

    auto compute = [&](int stage) {
        const uint32_t Ah = sb + stage * STAGE_B;
        const uint32_t Al = Ah + TILE_B;
        const uint32_t Wh = Al + TILE_B;
        const uint32_t Wl = Wh + TILE_B;
#pragma unroll
        for (int s = 0; s < 2; s++) {
            uint32_t ah[4][4], al[4][4], bh[4][2], bl[4][2];
#pragma unroll
            for (int mt = 0; mt < 4; mt++) {
                ldmx4(ah[mt], Ah + a_off + mt * 1280 + s * 32);
                ldmx4(al[mt], Al + a_off + mt * 1280 + s * 32);
            }
#pragma unroll
            for (int np = 0; np < 2; np++) {
                uint32_t r[4];
                ldmx4(r, Wh + b_off + np * 1280 + s * 32);
                bh[2 * np][0] = r[0]; bh[2 * np][1] = r[1];
                bh[2 * np + 1][0] = r[2]; bh[2 * np + 1][1] = r[3];
                ldmx4(r, Wl + b_off + np * 1280 + s * 32);
                bl[2 * np][0] = r[0]; bl[2 * np][1] = r[1];
                bl[2 * np + 1][0] = r[2]; bl[2 * np + 1][1] = r[3];
            }
#pragma unroll
            for (int mt = 0; mt < 4; mt++)
#pragma unroll
                for (int nt = 0; nt < 4; nt++) {
                    mma16816(acc[mt][nt], ah[mt], bh[nt]);
                    mma16816(acc[mt][nt], ah[mt], bl[nt]);
                    mma16816(acc[mt][nt], al[mt], bh[nt]);
                }
        }
    };

    load_stage(0, 0);
    for (int c = 0; c < 32; c++) {
        if (c + 1 < 32) {
            load_stage((c + 1) & 1, c + 1);
            CP_WAIT1();
        } else {
            CP_WAIT0();
        }
        __syncthreads();
        compute(c & 1);
        __syncthreads();
    }

    // Epilogue: bias + store float2 per fragment half
#pragma unroll
    for (int mt = 0; mt < 4; mt++) {
#pragma unroll
        for (int nt = 0; nt < 4; nt++) {
            const int row = bm + warpM * 64 + mt * 16 + (lane >> 2);
            const int col = bn + warpN * 32 + nt * 8 + (lane & 3) * 2;
            const float b0 = bias[col], b1 = bias[col + 1];
            float2 v0 = make_float2(acc[mt][nt][0] + b0, acc[mt][nt][1] + b1);
            float2 v1 = make_float2(acc[mt][nt][2] + b0, acc[mt][nt][3] + b1);
            *(float2*)&C[(size_t)row * DD + col] = v0;
            *(float2*)&C[(size_t)(row + 8) * DD + col] = v1;
        }
    }
}

// ---------------------------------------------------------------------------
// Causal flash attention, fp32, 4-way DK split.
// block 256: thread t -> query row (t>>2), dk-quarter (t&3) of 16 dims.
// Scores reduced over the 4-lane group via shfl_xor(1),(2).
// ---------------------------------------------------------------------------
__global__ __launch_bounds__(256, 3)
void attn_causal(const float* __restrict__ Q, const float* __restrict__ K,
                 const float* __restrict__ V, float* __restrict__ O)
{
    __shared__ float Ks[64 * 64];
    __shared__ float Vs[64 * 64];
    __shared__ float Sc[64 * 64];

    const int qt = blockIdx.x;
    const int bh = blockIdx.y;
    const int b = bh >> 4;
    const int h = bh & 15;
    const int t = threadIdx.x;
    const int row = t >> 2;
    const int half = t & 3;
    const int qg = qt * 64 + row;

    const float* qptr = Q + ((size_t)b * SS + qg) * DD + h * DKK + half * 16;
    float4 q4[4];
#pragma unroll
    for (int i = 0; i < 4; i++) q4[i] = *(const float4*)(qptr + i * 4);

    float4 a4[4];
#pragma unroll
    for (int i = 0; i < 4; i++) a4[i] = make_float4(0.f, 0.f, 0.f, 0.f);

    float m = -CUDART_INF_F;
    float l = 0.f;

    for (int kt = 0; kt <= qt; kt++) {
        const float* kbase = K + ((size_t)b * SS + kt * 64) * DD + h * DKK;
        const float* vbase = V + ((size_t)b * SS + kt * 64) * DD + h * DKK;
#pragma unroll
        for (int i = 0; i < 4; i++) {
            int f = t + i * 256;
            int krow = f >> 4;
            int d4 = (f & 15) * 4;
            *(float4*)&Ks[krow * 64 + d4] = *(const float4*)(kbase + (size_t)krow * DD + d4);
            *(float4*)&Vs[krow * 64 + d4] = *(const float4*)(vbase + (size_t)krow * DD + d4);
        }
        __syncthreads();

        const bool diag = (kt == qt);
        float tmax = -CUDART_INF_F;
        for (int k = 0; k < 64; k++) {
            const float4* kk = (const float4*)&Ks[k * 64 + half * 16];
            float4 s4 = make_float4(0.f, 0.f, 0.f, 0.f);
#pragma unroll
            for (int i = 0; i < 4; i++) {
                float4 kv = kk[i];
                s4.x += q4[i].x * kv.x; s4.y += q4[i].y * kv.y;
                s4.z += q4[i].z * kv.z; s4.w += q4[i].w * kv.w;
            }
            float s = (s4.x + s4.y) + (s4.z + s4.w);
            s += __shfl_xor_sync(0xffffffffu, s, 1);
            s += __shfl_xor_sync(0xffffffffu, s, 2);
            s *= 0.125f;                        // 1/sqrt(64)
            if (diag && k > row) s = -1e30f;
            if (half == 0) Sc[k * 64 + row] = s;
            tmax = fmaxf(tmax, s);
        }

        const float m_new = fmaxf(m, tmax);
        const float alpha = __expf(m - m_new);
        l *= alpha;
#pragma unroll
        for (int i = 0; i < 4; i++) {
            a4[i].x *= alpha; a4[i].y *= alpha;
            a4[i].z *= alpha; a4[i].w *= alpha;
        }
        m = m_new;
        __syncwarp();

        for (int k = 0; k < 64; k++) {
            float p = __expf(Sc[k * 64 + row] - m);
            l += p;
            const float4* vv = (const float4*)&Vs[k * 64 + half * 16];
#pragma unroll
            for (int i = 0; i < 4; i++) {
                float4 v = vv[i];
                a4[i].x += p * v.x; a4[i].y += p * v.y;
                a4[i].z += p * v.z; a4[i].w += p * v.w;
            }
        }
        __syncthreads();
    }

    const float inv = 1.f / l;
    float* optr = O + ((size_t)b * SS + qg) * DD + h * DKK + half * 16;
#pragma unroll
    for (int i = 0; i < 4; i++) {
        float4 o;
        o.x = a4[i].x * inv; o.y = a4[i].y * inv;
        o.z = a4[i].z * inv; o.w = a4[i].w * inv;
        *(float4*)(optr + i * 4) = o;
    }
}

// ---------------------------------------------------------------------------
// Launch. inputs: 0=query 1=key 2=value 3=mask 4=Wq 5=bq 6=Wk 7=bk 8=Wv 9=bv
//                 10=Wo 11=bo. mask is tril -> handled structurally.
// ---------------------------------------------------------------------------
extern "C" void kernel_launch(void* const* d_in, const int* in_sizes, int n_in,
                              void* d_out, int out_size)
{
    const float* X[3]  = {(const float*)d_in[0], (const float*)d_in[1],
                          (const float*)d_in[2]};
    const float* Wm[4] = {(const float*)d_in[4], (const float*)d_in[6],
                          (const float*)d_in[8], (const float*)d_in[10]};
    const float* Bv[4] = {(const float*)d_in[5], (const float*)d_in[7],
                          (const float*)d_in[9], (const float*)d_in[11]};
    float* out = (float*)d_out;

    float *gQ, *gK, *gV, *gA;
    __nv_bfloat16 *xhi, *xlo, *whi, *wlo;
    cudaGetSymbolAddress((void**)&gQ, g_Q);
    cudaGetSymbolAddress((void**)&gK, g_K);
    cudaGetSymbolAddress((void**)&gV, g_V);
    cudaGetSymbolAddress((void**)&gA, g_A);
    cudaGetSymbolAddress((void**)&xhi, g_Xhi);
    cudaGetSymbolAddress((void**)&xlo, g_Xlo);
    cudaGetSymbolAddress((void**)&whi, g_Whi);
    cudaGetSymbolAddress((void**)&wlo, g_Wlo);

    cudaFuncSetAttribute(gemm_mma, cudaFuncAttributeMaxDynamicSharedMemorySize, GEMM_SMEM);

    const int n4X = MTOT * DD / 4;
    const int n4W = DD * DD / 4;
    dim3 ggrid(DD / 128, MTOT / 128);   // (8, 32)
    float* outs[4] = {gQ, gK, gV, out};
    const float* ins[4] = {X[0], X[1], X[2], gA};

    for (int g = 0; g < 4; g++) {
        if (g == 3) {
            dim3 agrid(SS / 64, BB * HH);
            attn_causal<<<agrid, 256>>>(gQ, gK, gV, gA);
        }
        split_bf16<<<(n4W + 255) / 256, 256>>>(Wm[g], whi, wlo, n4W);
        split_bf16<<<(n4X + 255) / 256, 256>>>(ins[g], xhi, xlo, n4X);
        gemm_mma<<<ggrid, 256, GEMM_SMEM>>>(xhi, xlo, whi, wlo, Bv[g], outs[g]);
    }
}

// round 4
// speedup vs baseline: 1.0205x; 1.0205x over previous
#include <cuda_runtime.h>
#include <cuda_bf16.h>
#include <cstdint>
#include <math_constants.h>

#define BB 2
#define SS 2048
#define DD 1024
#define HH 16
#define DKK 64
#define MTOT (BB * SS)   // 4096

// ---------------------------------------------------------------------------
// Scratch (device globals; no allocation allowed)
// ---------------------------------------------------------------------------
__device__ float g_Q[MTOT * DD];
__device__ float g_K[MTOT * DD];
__device__ float g_V[MTOT * DD];
__device__ float g_A[MTOT * DD];
__device__ __nv_bfloat16 g_Xhi[MTOT * DD];
__device__ __nv_bfloat16 g_Xlo[MTOT * DD];
__device__ __nv_bfloat16 g_Whi[DD * DD];
__device__ __nv_bfloat16 g_Wlo[DD * DD];

// ---------------------------------------------------------------------------
// Helpers (sm_80-level PTX only: mma.sync / ldmatrix / cp.async)
// ---------------------------------------------------------------------------
__device__ __forceinline__ uint32_t smem_u32(const void* p) {
    uint32_t a;
    asm("{ .reg .u64 t; cvta.to.shared.u64 t, %1; cvt.u32.u64 %0, t; }" : "=r"(a) : "l"(p));
    return a;
}
__device__ __forceinline__ void cp16(uint32_t dst, const void* src) {
    asm volatile("cp.async.cg.shared.global [%0], [%1], 16;" :: "r"(dst), "l"(src));
}
#define CP_COMMIT() asm volatile("cp.async.commit_group;" ::: "memory")
#define CP_WAIT1()  asm volatile("cp.async.wait_group 1;" ::: "memory")
#define CP_WAIT0()  asm volatile("cp.async.wait_group 0;" ::: "memory")

__device__ __forceinline__ void ldmx4(uint32_t* r, uint32_t addr) {
    asm volatile("ldmatrix.sync.aligned.m8n8.x4.shared.b16 {%0,%1,%2,%3}, [%4];"
                 : "=r"(r[0]), "=r"(r[1]), "=r"(r[2]), "=r"(r[3]) : "r"(addr));
}
__device__ __forceinline__ void mma16816(float* c, const uint32_t* a, const uint32_t* b) {
    asm volatile(
        "mma.sync.aligned.m16n8k16.row.col.f32.bf16.bf16.f32 "
        "{%0,%1,%2,%3}, {%4,%5,%6,%7}, {%8,%9}, {%0,%1,%2,%3};"
        : "+f"(c[0]), "+f"(c[1]), "+f"(c[2]), "+f"(c[3])
        : "r"(a[0]), "r"(a[1]), "r"(a[2]), "r"(a[3]), "r"(b[0]), "r"(b[1]));
}

// ---------------------------------------------------------------------------
// Split fp32 -> bf16 hi/lo  (x = hi + lo + O(2^-18 x))
// ---------------------------------------------------------------------------
__global__ void split_bf16(const float* __restrict__ x, __nv_bfloat16* __restrict__ hi,
                           __nv_bfloat16* __restrict__ lo, int n4)
{
    int i = blockIdx.x * blockDim.x + threadIdx.x;
    if (i >= n4) return;
    float4 v = ((const float4*)x)[i];
    float vv[4] = {v.x, v.y, v.z, v.w};
    union { __nv_bfloat16 b[4]; uint2 u; } H, L;
#pragma unroll
    for (int j = 0; j < 4; j++) {
        __nv_bfloat16 h = __float2bfloat16(vv[j]);
        H.b[j] = h;
        L.b[j] = __float2bfloat16(vv[j] - __bfloat162float(h));
    }
    ((uint2*)hi)[i] = H.u;
    ((uint2*)lo)[i] = L.u;
}

// ---------------------------------------------------------------------------
// HMMA bf16x3 GEMM: C[4096,1024] = A @ W^T + bias
// CTA 128x128, BK=32, 8 warps in 2(M)x4(N), warp tile 64x32.
// smem tile layout: 128 rows x 32 bf16 (64B) padded to 80B stride
// (conflict-free for ldmatrix: banks(20r+c) distinct over r=0..7).
// Double-buffered with cp.async. Tiles per stage: Ahi, Alo, Whi, Wlo.
// ---------------------------------------------------------------------------
#define TILE_B 10240               // 128 * 80
#define STAGE_B (4 * TILE_B)       // 40960
#define GEMM_SMEM (2 * STAGE_B)    // 81920

__global__ __launch_bounds__(256)
void gemm_mma(const __nv_bfloat16* __restrict__ Ahi, const __nv_bfloat16* __restrict__ Alo,
              const __nv_bfloat16* __restrict__ Whi, const __nv_bfloat16* __restrict__ Wlo,
              const float* __restrict__ bias, float* __restrict__ C)
{
    extern __shared__ __align__(128) char smem[];
    const uint32_t sb = smem_u32(smem);
    const int tid = threadIdx.x;
    const int wid = tid >> 5;
    const int lane = tid & 31;
    const int bm = blockIdx.y * 128;
    const int bn = blockIdx.x * 128;
    const int warpM = wid >> 2;    // 0..1
    const int warpN = wid & 3;     // 0..3

    const char* srcs[4] = {
        (const char*)(Ahi + (size_t)bm * DD),
        (const char*)(Alo + (size_t)bm * DD),
        (const char*)(Whi + (size_t)bn * DD),
        (const char*)(Wlo + (size_t)bn * DD)
    };

    float acc[4][4][4];
#pragma unroll
    for (int i = 0; i < 4; i++)
#pragma unroll
        for (int j = 0; j < 4; j++)
#pragma unroll
            for (int q = 0; q < 4; q++) acc[i][j][q] = 0.f;

    // ldmatrix lane addressing
    const int lr = lane & 7;
    const int lb8 = (lane >> 3) & 1;
    const int lb16 = (lane >> 4) & 1;
    // A-type (rows = output rows, 4 tiles of 16): row = lr + lb8*8, khalf = lb16
    const uint32_t a_off = (uint32_t)((lr + lb8 * 8) * 80 + lb16 * 16) + (uint32_t)(warpM * 64 * 80);
    // B-type (rows = n, pair of ntiles): n = lr + lb16*8, khalf = lb8
    const uint32_t b_off = (uint32_t)((lr + lb16 * 8) * 80 + lb8 * 16) + (uint32_t)(warpN * 32 * 80);

    // --- stage loader ---
    auto load_stage = [&](int stage, int c) {
#pragma unroll
        for (int t = 0; t < 4; t++) {
            uint32_t base = sb + stage * STAGE_B + t * TILE_B;
            const char* g = srcs[t] + c * 64;       // c*32 bf16 = 64 bytes
#pragma unroll
            for (int j = 0; j < 2; j++) {
                int chunk = tid + j * 256;          // 0..511
                int row = chunk >> 2;
                int cw = chunk & 3;
                cp16(base + (uint32_t)(row * 80 + cw * 16), g + (size_t)row * 2048 + cw * 16);
            }
        }
        CP_COMMIT();
    };

    auto compute = [&](int stage) {
        const uint32_t Ah = sb + stage * STAGE_B;
        const uint32_t Al = Ah + TILE_B;
        const uint32_t Wh = Al + TILE_B;
        const uint32_t Wl = Wh + TILE_B;
#pragma unroll
        for (int s = 0; s < 2; s++) {
            uint32_t ah[4][4], al[4][4], bh[4][2], bl[4][2];
#pragma unroll
            for (int mt = 0; mt < 4; mt++) {
                ldmx4(ah[mt], Ah + a_off + mt * 1280 + s * 32);
                ldmx4(al[mt], Al + a_off + mt * 1280 + s * 32);
            }
#pragma unroll
            for (int np = 0; np < 2; np++) {
                uint32_t r[4];
                ldmx4(r, Wh + b_off + np * 1280 + s * 32);
                bh[2 * np][0] = r[0]; bh[2 * np][1] = r[1];
                bh[2 * np + 1][0] = r[2]; bh[2 * np + 1][1] = r[3];
                ldmx4(r, Wl + b_off + np * 1280 + s * 32);
                bl[2 * np][0] = r[0]; bl[2 * np][1] = r[1];
                bl[2 * np + 1][0] = r[2]; bl[2 * np + 1][1] = r[3];
            }
#pragma unroll
            for (int mt = 0; mt < 4; mt++)
#pragma unroll
                for (int nt = 0; nt < 4; nt++) {
                    mma16816(acc[mt][nt], ah[mt], bh[nt]);
                    mma16816(acc[mt][nt], ah[mt], bl[nt]);
                    mma16816(acc[mt][nt], al[mt], bh[nt]);
                }
        }
    };

    load_stage(0, 0);
    for (int c = 0; c < 32; c++) {
        if (c + 1 < 32) {
            load_stage((c + 1) & 1, c + 1);
            CP_WAIT1();
        } else {
            CP_WAIT0();
        }
        __syncthreads();
        compute(c & 1);
        __syncthreads();
    }

    // Epilogue: bias + store float2 per fragment half
#pragma unroll
    for (int mt = 0; mt < 4; mt++) {
#pragma unroll
        for (int nt = 0; nt < 4; nt++) {
            const int row = bm + warpM * 64 + mt * 16 + (lane >> 2);
            const int col = bn + warpN * 32 + nt * 8 + (lane & 3) * 2;
            const float b0 = bias[col], b1 = bias[col + 1];
            float2 v0 = make_float2(acc[mt][nt][0] + b0, acc[mt][nt][1] + b1);
            float2 v1 = make_float2(acc[mt][nt][2] + b0, acc[mt][nt][3] + b1);
            *(float2*)&C[(size_t)row * DD + col] = v0;
            *(float2*)&C[(size_t)(row + 8) * DD + col] = v1;
        }
    }
}

// ---------------------------------------------------------------------------
// Causal flash attention, fp32, 4-way DK split.
// block 256: thread t -> query row (t>>2), dk-quarter (t&3) of 16 dims.
// Scores reduced over the 4-lane group via shfl_xor(1),(2).
// ---------------------------------------------------------------------------
__global__ __launch_bounds__(256, 3)
void attn_causal(const float* __restrict__ Q, const float* __restrict__ K,
                 const float* __restrict__ V, float* __restrict__ O)
{
    __shared__ float Ks[64 * 64];
    __shared__ float Vs[64 * 64];
    __shared__ float Sc[64 * 64];

    const int qt = blockIdx.x;
    const int bh = blockIdx.y;
    const int b = bh >> 4;
    const int h = bh & 15;
    const int t = threadIdx.x;
    const int row = t >> 2;
    const int half = t & 3;
    const int qg = qt * 64 + row;

    const float* qptr = Q + ((size_t)b * SS + qg) * DD + h * DKK + half * 16;
    float4 q4[4];
#pragma unroll
    for (int i = 0; i < 4; i++) q4[i] = *(const float4*)(qptr + i * 4);

    float4 a4[4];
#pragma unroll
    for (int i = 0; i < 4; i++) a4[i] = make_float4(0.f, 0.f, 0.f, 0.f);

    float m = -CUDART_INF_F;
    float l = 0.f;

    for (int kt = 0; kt <= qt; kt++) {
        const float* kbase = K + ((size_t)b * SS + kt * 64) * DD + h * DKK;
        const float* vbase = V + ((size_t)b * SS + kt * 64) * DD + h * DKK;
#pragma unroll
        for (int i = 0; i < 4; i++) {
            int f = t + i * 256;
            int krow = f >> 4;
            int d4 = (f & 15) * 4;
            *(float4*)&Ks[krow * 64 + d4] = *(const float4*)(kbase + (size_t)krow * DD + d4);
            *(float4*)&Vs[krow * 64 + d4] = *(const float4*)(vbase + (size_t)krow * DD + d4);
        }
        __syncthreads();

        const bool diag = (kt == qt);
        float tmax = -CUDART_INF_F;
        for (int k = 0; k < 64; k++) {
            const float4* kk = (const float4*)&Ks[k * 64 + half * 16];
            float4 s4 = make_float4(0.f, 0.f, 0.f, 0.f);
#pragma unroll
            for (int i = 0; i < 4; i++) {
                float4 kv = kk[i];
                s4.x += q4[i].x * kv.x; s4.y += q4[i].y * kv.y;
                s4.z += q4[i].z * kv.z; s4.w += q4[i].w * kv.w;
            }
            float s = (s4.x + s4.y) + (s4.z + s4.w);
            s += __shfl_xor_sync(0xffffffffu, s, 1);
            s += __shfl_xor_sync(0xffffffffu, s, 2);
            s *= 0.125f;                        // 1/sqrt(64)
            if (diag && k > row) s = -1e30f;
            if (half == 0) Sc[k * 64 + row] = s;
            tmax = fmaxf(tmax, s);
        }

        const float m_new = fmaxf(m, tmax);
        const float alpha = __expf(m - m_new);
        l *= alpha;
#pragma unroll
        for (int i = 0; i < 4; i++) {
            a4[i].x *= alpha; a4[i].y *= alpha;
            a4[i].z *= alpha; a4[i].w *= alpha;
        }
        m = m_new;
        __syncwarp();

        for (int k = 0; k < 64; k++) {
            float p = __expf(Sc[k * 64 + row] - m);
            l += p;
            const float4* vv = (const float4*)&Vs[k * 64 + half * 16];
#pragma unroll
            for (int i = 0; i < 4; i++) {
                float4 v = vv[i];
                a4[i].x += p * v.x; a4[i].y += p * v.y;
                a4[i].z += p * v.z; a4[i].w += p * v.w;
            }
        }
        __syncthreads();
    }

    const float inv = 1.f / l;
    float* optr = O + ((size_t)b * SS + qg) * DD + h * DKK + half * 16;
#pragma unroll
    for (int i = 0; i < 4; i++) {
        float4 o;
        o.x = a4[i].x * inv; o.y = a4[i].y * inv;
        o.z = a4[i].z * inv; o.w = a4[i].w * inv;
        *(float4*)(optr + i * 4) = o;
    }
}

// ---------------------------------------------------------------------------
// Launch. inputs: 0=query 1=key 2=value 3=mask 4=Wq 5=bq 6=Wk 7=bk 8=Wv 9=bv
//                 10=Wo 11=bo. mask is tril -> handled structurally.
// ---------------------------------------------------------------------------
extern "C" void kernel_launch(void* const* d_in, const int* in_sizes, int n_in,
                              void* d_out, int out_size)
{
    const float* X[3]  = {(const float*)d_in[0], (const float*)d_in[1],
                          (const float*)d_in[2]};
    const float* Wm[4] = {(const float*)d_in[4], (const float*)d_in[6],
                          (const float*)d_in[8], (const float*)d_in[10]};
    const float* Bv[4] = {(const float*)d_in[5], (const float*)d_in[7],
                          (const float*)d_in[9], (const float*)d_in[11]};
    float* out = (float*)d_out;

    float *gQ, *gK, *gV, *gA;
    __nv_bfloat16 *xhi, *xlo, *whi, *wlo;
    cudaGetSymbolAddress((void**)&gQ, g_Q);
    cudaGetSymbolAddress((void**)&gK, g_K);
    cudaGetSymbolAddress((void**)&gV, g_V);
    cudaGetSymbolAddress((void**)&gA, g_A);
    cudaGetSymbolAddress((void**)&xhi, g_Xhi);
    cudaGetSymbolAddress((void**)&xlo, g_Xlo);
    cudaGetSymbolAddress((void**)&whi, g_Whi);
    cudaGetSymbolAddress((void**)&wlo, g_Wlo);

    cudaFuncSetAttribute(gemm_mma, cudaFuncAttributeMaxDynamicSharedMemorySize, GEMM_SMEM);

    const int n4X = MTOT * DD / 4;
    const int n4W = DD * DD / 4;
    dim3 ggrid(DD / 128, MTOT / 128);   // (8, 32)
    float* outs[4] = {gQ, gK, gV, out};
    const float* ins[4] = {X[0], X[1], X[2], gA};

    for (int g = 0; g < 4; g++) {
        if (g == 3) {
            dim3 agrid(SS / 64, BB * HH);
            attn_causal<<<agrid, 256>>>(gQ, gK, gV, gA);
        }
        split_bf16<<<(n4W + 255) / 256, 256>>>(Wm[g], whi, wlo, n4W);
        split_bf16<<<(n4X + 255) / 256, 256>>>(ins[g], xhi, xlo, n4X);
        gemm_mma<<<ggrid, 256, GEMM_SMEM>>>(xhi, xlo, whi, wlo, Bv[g], outs[g]);
    }
}